// round 9
// baseline (speedup 1.0000x reference)
#include <cuda_runtime.h>
#include <cuda_bf16.h>
#include <cstdint>
#include <cstddef>

// ---------------- problem constants ----------------
constexpr int kC  = 1024;
constexpr int kE  = 8;
constexpr int kH  = 4096;
constexpr int kN  = 8192;
constexpr int kBM = 128;               // CTA M tile
constexpr int kBN = 128;               // CTA N tile
constexpr int kRMax = kN + kE * kBM;   // 9216 padded rows
constexpr int kNRT  = kRMax / kBM;     // 72 row tiles
constexpr int kRegB  = kBM * 48;       // 6144 B per region (128 rows x 48B stride)
constexpr int kStageB = 4 * kRegB;     // Ahi|Alo|Bhi|Blo = 24576 B
constexpr int kDynSmem = 2 * kStageB;  // 49152 B = 48KB (no opt-in needed)

// ---------------- device scratch: SAME byte sizes as the passing round -------
// g_xg: 37.7MB reinterpreted as hi-plane + lo-plane of packed bf16 pairs.
// g_h : 151MB  reinterpreted the same way.
__device__ uint32_t g_xg[(size_t)kRMax * kC];
__device__ uint32_t g_h [(size_t)kRMax * kH];
__device__ float g_prob[kN];
__device__ int   g_idx[kN];
__device__ int   g_perm[kRMax];
__device__ int   g_cnt[kE];
__device__ int   g_cur[kE];
__device__ int   g_poff[kE + 1];

constexpr size_t kXPlane = (size_t)kRMax * (kC / 2);   // u32 per plane
constexpr size_t kHPlane = (size_t)kRMax * (kH / 2);

// ---------------- helpers ----------------
__device__ __forceinline__ uint32_t smem_u32(const void* p) {
    uint32_t a;
    asm("{ .reg .u64 t; cvta.to.shared.u64 t, %1; cvt.u32.u64 %0, t; }" : "=r"(a) : "l"(p));
    return a;
}
__device__ __forceinline__ void cpa16(uint32_t dst, const void* src) {
    asm volatile("cp.async.cg.shared.global [%0], [%1], 16;" :: "r"(dst), "l"(src));
}
#define CP_COMMIT() asm volatile("cp.async.commit_group;" ::: "memory")
#define CP_WAIT0()  asm volatile("cp.async.wait_group 0;" ::: "memory")

#define LDSM4(r, a) \
    asm volatile("ldmatrix.sync.aligned.m8n8.x4.shared.b16 {%0,%1,%2,%3}, [%4];" \
                 : "=r"((r)[0]), "=r"((r)[1]), "=r"((r)[2]), "=r"((r)[3]) : "r"(a))

__device__ __forceinline__ void mma16816(float* c, const uint32_t* a, const uint32_t* b) {
    asm volatile(
        "mma.sync.aligned.m16n8k16.row.col.f32.bf16.bf16.f32 "
        "{%0,%1,%2,%3}, {%4,%5,%6,%7}, {%8,%9}, {%0,%1,%2,%3};\n"
        : "+f"(c[0]), "+f"(c[1]), "+f"(c[2]), "+f"(c[3])
        : "r"(a[0]), "r"(a[1]), "r"(a[2]), "r"(a[3]), "r"(b[0]), "r"(b[1]));
}

__device__ __forceinline__ float geluf(float v) {
    return 0.5f * v * (1.0f + erff(v * 0.70710678118654752f));
}
__device__ __forceinline__ void split_pack(float v0, float v1, uint32_t& hp, uint32_t& lp) {
    __nv_bfloat16 h0 = __float2bfloat16(v0);
    __nv_bfloat16 h1 = __float2bfloat16(v1);
    __nv_bfloat16 l0 = __float2bfloat16(v0 - __bfloat162float(h0));
    __nv_bfloat16 l1 = __float2bfloat16(v1 - __bfloat162float(h1));
    hp = (uint32_t)__bfloat16_as_ushort(h0) | ((uint32_t)__bfloat16_as_ushort(h1) << 16);
    lp = (uint32_t)__bfloat16_as_ushort(l0) | ((uint32_t)__bfloat16_as_ushort(l1) << 16);
}

// ---------------- small kernels ----------------
__global__ void reset_kernel() {
    int t = threadIdx.x;
    if (t < kE) { g_cnt[t] = 0; g_cur[t] = 0; }
}

__global__ void router_kernel(const float* __restrict__ x,
                              const float* __restrict__ Wr,
                              const float* __restrict__ br) {
    int tok  = (blockIdx.x * blockDim.x + threadIdx.x) >> 5;
    int lane = threadIdx.x & 31;
    if (tok >= kN) return;
    const float* xr = x + (size_t)tok * kC;
    float acc[kE];
#pragma unroll
    for (int e = 0; e < kE; e++) acc[e] = 0.f;
    for (int c = lane; c < kC; c += 32) {
        float xv = xr[c];
        const float4* w = (const float4*)(Wr + (size_t)c * kE);
        float4 w0 = w[0], w1 = w[1];
        acc[0] += xv * w0.x; acc[1] += xv * w0.y; acc[2] += xv * w0.z; acc[3] += xv * w0.w;
        acc[4] += xv * w1.x; acc[5] += xv * w1.y; acc[6] += xv * w1.z; acc[7] += xv * w1.w;
    }
#pragma unroll
    for (int e = 0; e < kE; e++)
        for (int o = 16; o > 0; o >>= 1)
            acc[e] += __shfl_xor_sync(0xffffffffu, acc[e], o);
    if (lane == 0) {
        float m = -1e30f; int bi = 0;
#pragma unroll
        for (int e = 0; e < kE; e++) {
            acc[e] += br[e];
            if (acc[e] > m) { m = acc[e]; bi = e; }
        }
        float s = 0.f;
#pragma unroll
        for (int e = 0; e < kE; e++) s += expf(acc[e] - m);
        g_prob[tok] = 1.f / s;
        g_idx[tok]  = bi;
        atomicAdd(&g_cnt[bi], 1);
    }
}

__global__ void offsets_kernel(float* aux_out) {
    if (threadIdx.x == 0) {
        int p = 0; float s = 0.f;
#pragma unroll
        for (int e = 0; e < kE; e++) {
            g_poff[e] = p;
            int c = g_cnt[e];
            p += (c + kBM - 1) / kBM * kBM;
            float f = (float)c / (float)kN;
            float d = f - (1.0f / (float)kE);
            s += d * d;
        }
        g_poff[kE] = p;
        if (aux_out) *aux_out = s / (float)kE;
    }
}

// gather: x -> hi/lo planes of packed bf16 pairs (same buffer bytes as fp32 copy)
__global__ void gather_kernel(const float* __restrict__ x) {
    int tok  = (blockIdx.x * blockDim.x + threadIdx.x) >> 5;
    int lane = threadIdx.x & 31;
    if (tok >= kN) return;
    int e = g_idx[tok];
    int pos = 0;
    if (lane == 0) pos = g_poff[e] + atomicAdd(&g_cur[e], 1);
    pos = __shfl_sync(0xffffffffu, pos, 0);
    if (lane == 0) g_perm[pos] = tok;
    const float2* src = (const float2*)(x + (size_t)tok * kC);
    uint32_t* dh = g_xg + (size_t)pos * (kC / 2);
    uint32_t* dl = dh + kXPlane;
#pragma unroll
    for (int g = 0; g < 16; g++) {
        float2 v = src[g * 32 + lane];
        uint32_t hp, lp;
        split_pack(v.x, v.y, hp, lp);
        dh[g * 32 + lane] = hp;
        dl[g * 32 + lane] = lp;
    }
}

// ---------------- grouped GEMM: A pre-split (cp.async), B fp32 + in-kernel split
// SECOND=false: g_h(planes) = gelu(xg @ W1[e] + b1)
// SECOND=true : out[perm[r]] = prob * (h @ W2[e] + b2)
template <bool SECOND>
__global__ __launch_bounds__(256)
void moe_mma(const float* __restrict__ Wsrc, const float* __restrict__ bias,
             float* __restrict__ OutP) {
    constexpr int KDIM = SECOND ? kH : kC;
    constexpr int ND   = SECOND ? kC : kH;
    constexpr int KB   = KDIM / 16;
    constexpr int KW   = KDIM / 2;                 // u32 per row in a plane

    extern __shared__ char smc[];
    const uint32_t sb = smem_u32(smc);

    const int rt = blockIdx.y, bx = blockIdx.x;
    const int row0 = rt * kBM;
    if (row0 >= g_poff[kE]) return;
    int e = 0;
    while (e < kE - 1 && row0 >= g_poff[e + 1]) e++;

    const uint32_t* Ahi = (SECOND ? g_h : g_xg) + (size_t)row0 * KW;
    const uint32_t* Alo = Ahi + (SECOND ? kHPlane : kXPlane);
    const float*    B   = Wsrc + (size_t)e * KDIM * ND + (size_t)bx * kBN;

    const int tid  = threadIdx.x;
    const int warp = tid >> 5;
    const int lane = tid & 31;
    const int wm   = warp & 3;
    const int wn   = warp >> 2;

    // A fill: thread -> (row, 16B half); one cp.async per plane
    const int arow = tid >> 1, ah = tid & 1;
    const uint32_t* AhiP = Ahi + (size_t)arow * KW + ah * 4;
    const uint32_t* AloP = Alo + (size_t)arow * KW + ah * 4;
    const uint32_t adst  = (uint32_t)arow * 48u + (uint32_t)ah * 16u;

    // B fill: thread -> (n col, k octet)
    const int bn = tid & 127, bkp = tid >> 7;
    const float* Bload = B + (size_t)bkp * 8 * ND + bn;

    auto cpA = [&](int kb, int s) {
        uint32_t base = sb + (uint32_t)s * kStageB + adst;
        cpa16(base, AhiP + kb * 8);
        cpa16(base + (uint32_t)kRegB, AloP + kb * 8);
    };
    float rb[8], rb2[8];
    auto loadB = [&](int kb, float* b) {
#pragma unroll
        for (int i = 0; i < 8; i++)
            b[i] = Bload[(size_t)(kb * 16 + i) * ND];
    };
    auto storeB = [&](int s, const float* b) {
        char* base = smc + (size_t)s * kStageB + 2 * kRegB + (size_t)bn * 48 + bkp * 16;
#pragma unroll
        for (int i = 0; i < 4; i++) {
            uint32_t hp, lp;
            split_pack(b[2 * i], b[2 * i + 1], hp, lp);
            *(uint32_t*)(base + i * 4)         = hp;
            *(uint32_t*)(base + kRegB + i * 4) = lp;
        }
    };

    // ldmatrix byte offsets within one region (row stride 48B)
    uint32_t offA[2], offB[4];
#pragma unroll
    for (int i = 0; i < 2; i++) {
        uint32_t row = wm * 32 + i * 16 + ((lane >> 3) & 1) * 8 + (lane & 7);
        offA[i] = row * 48 + (lane >> 4) * 16;
    }
#pragma unroll
    for (int jp = 0; jp < 4; jp++) {
        uint32_t row = wn * 64 + jp * 16 + (lane >> 4) * 8 + (lane & 7);
        offB[jp] = row * 48 + ((lane >> 3) & 1) * 16;
    }

    float acc[2][8][4];
#pragma unroll
    for (int i = 0; i < 2; i++)
#pragma unroll
        for (int j = 0; j < 8; j++)
#pragma unroll
            for (int q = 0; q < 4; q++) acc[i][j][q] = 0.f;

    // prologue: stage0 = block 0
    loadB(0, rb);
    cpA(0, 0); CP_COMMIT();
    storeB(0, rb);
    loadB(1, rb);
    CP_WAIT0();
    __syncthreads();

    for (int kb = 0; kb < KB; kb++) {
        const int s = kb & 1;
        if (kb + 1 < KB) {
            cpA(kb + 1, s ^ 1); CP_COMMIT();
            storeB(s ^ 1, rb);
        }
        if (kb + 2 < KB) loadB(kb + 2, rb2);

        const uint32_t st = sb + (uint32_t)s * kStageB;
        uint32_t ahi[2][4], alo[2][4], bhi[4][4], blo[4][4];
#pragma unroll
        for (int i = 0; i < 2; i++) {
            LDSM4(ahi[i], st + offA[i]);
            LDSM4(alo[i], st + (uint32_t)kRegB + offA[i]);
        }
#pragma unroll
        for (int jp = 0; jp < 4; jp++) {
            LDSM4(bhi[jp], st + 2u * kRegB + offB[jp]);
            LDSM4(blo[jp], st + 3u * kRegB + offB[jp]);
        }
#pragma unroll
        for (int i = 0; i < 2; i++)
#pragma unroll
            for (int j = 0; j < 8; j++) {
                int jp = j >> 1, s2 = (j & 1) * 2;
                mma16816(acc[i][j], ahi[i], &bhi[jp][s2]);
                mma16816(acc[i][j], ahi[i], &blo[jp][s2]);
                mma16816(acc[i][j], alo[i], &bhi[jp][s2]);
            }
#pragma unroll
        for (int q = 0; q < 8; q++) rb[q] = rb2[q];
        CP_WAIT0();
        __syncthreads();
    }

    // ---------------- epilogue ----------------
    const int realEnd = g_poff[e] + g_cnt[e];
    const float* biasE = bias + (size_t)e * ND + (size_t)bx * kBN;
    const int r0 = wm * 32 + (lane >> 2);
    const int c0 = (lane & 3) * 2;

#pragma unroll
    for (int i = 0; i < 2; i++)
#pragma unroll
        for (int hh = 0; hh < 2; hh++) {
            int r = row0 + r0 + i * 16 + hh * 8;
            if (r >= realEnd) continue;
            if (!SECOND) {
                uint32_t* hrh = g_h + (size_t)r * (kH / 2) + (size_t)bx * (kBN / 2);
                uint32_t* hrl = hrh + kHPlane;
#pragma unroll
                for (int j = 0; j < 8; j++) {
                    int col = wn * 64 + j * 8 + c0;
                    float v0 = geluf(acc[i][j][hh * 2 + 0] + biasE[col]);
                    float v1 = geluf(acc[i][j][hh * 2 + 1] + biasE[col + 1]);
                    uint32_t hp, lp;
                    split_pack(v0, v1, hp, lp);
                    hrh[col >> 1] = hp;
                    hrl[col >> 1] = lp;
                }
            } else {
                int n = g_perm[r];
                float sc = g_prob[n];
                float* orow = OutP + (size_t)n * kC + (size_t)bx * kBN;
#pragma unroll
                for (int j = 0; j < 8; j++) {
                    int col = wn * 64 + j * 8 + c0;
                    float2 v;
                    v.x = (acc[i][j][hh * 2 + 0] + biasE[col]) * sc;
                    v.y = (acc[i][j][hh * 2 + 1] + biasE[col + 1]) * sc;
                    *(float2*)(orow + col) = v;
                }
            }
        }
}

// ---------------- launch ----------------
extern "C" void kernel_launch(void* const* d_in, const int* in_sizes, int n_in,
                              void* d_out, int out_size) {
    const float* x  = (const float*)d_in[0];
    const float* Wr = (const float*)d_in[1];
    const float* br = (const float*)d_in[2];
    const float* W1 = (const float*)d_in[3];
    const float* b1 = (const float*)d_in[4];
    const float* W2 = (const float*)d_in[5];
    const float* b2 = (const float*)d_in[6];
    float* out = (float*)d_out;
    (void)n_in;

    reset_kernel<<<1, 32>>>();
    router_kernel<<<kN / 8, 256>>>(x, Wr, br);
    float* auxp = (out_size > kN * kC) ? out + (size_t)kN * kC : nullptr;
    offsets_kernel<<<1, 1>>>(auxp);
    gather_kernel<<<kN / 8, 256>>>(x);

    moe_mma<false><<<dim3(kH / kBN, kNRT), 256, kDynSmem>>>(W1, b1, nullptr);
    moe_mma<true ><<<dim3(kC / kBN, kNRT), 256, kDynSmem>>>(W2, b2, out);
}

// round 10
// speedup vs baseline: 1.2041x; 1.2041x over previous
#include <cuda_runtime.h>
#include <cuda_bf16.h>
#include <cstdint>
#include <cstddef>

// ---------------- problem constants ----------------
constexpr int kC  = 1024;
constexpr int kE  = 8;
constexpr int kH  = 4096;
constexpr int kN  = 8192;
constexpr int kBM = 128;               // CTA M tile
constexpr int kBN = 128;               // CTA N tile
constexpr int kRMax = kN + kE * kBM;   // 9216 padded rows
constexpr int kNRT  = kRMax / kBM;     // 72 row tiles
constexpr int kRegB  = kBM * 48;       // 6144 B per region (128 rows x 48B stride)
constexpr int kStageB = 4 * kRegB;     // Ahi|Alo|Bhi|Blo = 24576 B
constexpr int kDynSmem = 2 * kStageB;  // 49152 B = 48KB (no opt-in needed)

// ---------------- device scratch (189MB profile, proven safe) ----------------
// g_xg / g_h hold hi-plane then lo-plane of packed bf16 pairs (2 per u32).
__device__ uint32_t g_xg[(size_t)kRMax * kC];
__device__ uint32_t g_h [(size_t)kRMax * kH];
__device__ float g_prob[kN];
__device__ int   g_idx[kN];
__device__ int   g_perm[kRMax];
__device__ int   g_cnt[kE];
__device__ int   g_cur[kE];
__device__ int   g_poff[kE + 1];

constexpr size_t kXPlane = (size_t)kRMax * (kC / 2);   // u32 per plane
constexpr size_t kHPlane = (size_t)kRMax * (kH / 2);

// ---------------- helpers ----------------
__device__ __forceinline__ uint32_t smem_u32(const void* p) {
    uint32_t a;
    asm("{ .reg .u64 t; cvta.to.shared.u64 t, %1; cvt.u32.u64 %0, t; }" : "=r"(a) : "l"(p));
    return a;
}

#define LDSM4(r, a) \
    asm volatile("ldmatrix.sync.aligned.m8n8.x4.shared.b16 {%0,%1,%2,%3}, [%4];" \
                 : "=r"((r)[0]), "=r"((r)[1]), "=r"((r)[2]), "=r"((r)[3]) : "r"(a))

__device__ __forceinline__ void mma16816(float* c, const uint32_t* a, const uint32_t* b) {
    asm volatile(
        "mma.sync.aligned.m16n8k16.row.col.f32.bf16.bf16.f32 "
        "{%0,%1,%2,%3}, {%4,%5,%6,%7}, {%8,%9}, {%0,%1,%2,%3};\n"
        : "+f"(c[0]), "+f"(c[1]), "+f"(c[2]), "+f"(c[3])
        : "r"(a[0]), "r"(a[1]), "r"(a[2]), "r"(a[3]), "r"(b[0]), "r"(b[1]));
}

__device__ __forceinline__ float geluf(float v) {
    return 0.5f * v * (1.0f + erff(v * 0.70710678118654752f));
}
// pack {v1,v0} -> bf16x2 (v0 in low half), RN rounding (same as __float2bfloat16)
__device__ __forceinline__ uint32_t cvt_bf16x2(float v0, float v1) {
    uint32_t r;
    asm("cvt.rn.bf16x2.f32 %0, %1, %2;" : "=r"(r) : "f"(v1), "f"(v0));
    return r;
}
__device__ __forceinline__ void split_pack(float v0, float v1, uint32_t& hp, uint32_t& lp) {
    hp = cvt_bf16x2(v0, v1);
    float h0 = __uint_as_float(hp << 16);
    float h1 = __uint_as_float(hp & 0xFFFF0000u);
    lp = cvt_bf16x2(v0 - h0, v1 - h1);
}

// ---------------- small kernels ----------------
__global__ void reset_kernel() {
    int t = threadIdx.x;
    if (t < kE) { g_cnt[t] = 0; g_cur[t] = 0; }
}

__global__ void router_kernel(const float* __restrict__ x,
                              const float* __restrict__ Wr,
                              const float* __restrict__ br) {
    int tok  = (blockIdx.x * blockDim.x + threadIdx.x) >> 5;
    int lane = threadIdx.x & 31;
    if (tok >= kN) return;
    const float* xr = x + (size_t)tok * kC;
    float acc[kE];
#pragma unroll
    for (int e = 0; e < kE; e++) acc[e] = 0.f;
    for (int c = lane; c < kC; c += 32) {
        float xv = xr[c];
        const float4* w = (const float4*)(Wr + (size_t)c * kE);
        float4 w0 = w[0], w1 = w[1];
        acc[0] += xv * w0.x; acc[1] += xv * w0.y; acc[2] += xv * w0.z; acc[3] += xv * w0.w;
        acc[4] += xv * w1.x; acc[5] += xv * w1.y; acc[6] += xv * w1.z; acc[7] += xv * w1.w;
    }
#pragma unroll
    for (int e = 0; e < kE; e++)
        for (int o = 16; o > 0; o >>= 1)
            acc[e] += __shfl_xor_sync(0xffffffffu, acc[e], o);
    if (lane == 0) {
        float m = -1e30f; int bi = 0;
#pragma unroll
        for (int e = 0; e < kE; e++) {
            acc[e] += br[e];
            if (acc[e] > m) { m = acc[e]; bi = e; }
        }
        float s = 0.f;
#pragma unroll
        for (int e = 0; e < kE; e++) s += expf(acc[e] - m);
        g_prob[tok] = 1.f / s;
        g_idx[tok]  = bi;
        atomicAdd(&g_cnt[bi], 1);
    }
}

__global__ void offsets_kernel(float* aux_out) {
    if (threadIdx.x == 0) {
        int p = 0; float s = 0.f;
#pragma unroll
        for (int e = 0; e < kE; e++) {
            g_poff[e] = p;
            int c = g_cnt[e];
            p += (c + kBM - 1) / kBM * kBM;
            float f = (float)c / (float)kN;
            float d = f - (1.0f / (float)kE);
            s += d * d;
        }
        g_poff[kE] = p;
        if (aux_out) *aux_out = s / (float)kE;
    }
}

// gather: x -> hi/lo planes of packed bf16 pairs
__global__ void gather_kernel(const float* __restrict__ x) {
    int tok  = (blockIdx.x * blockDim.x + threadIdx.x) >> 5;
    int lane = threadIdx.x & 31;
    if (tok >= kN) return;
    int e = g_idx[tok];
    int pos = 0;
    if (lane == 0) pos = g_poff[e] + atomicAdd(&g_cur[e], 1);
    pos = __shfl_sync(0xffffffffu, pos, 0);
    if (lane == 0) g_perm[pos] = tok;
    const float2* src = (const float2*)(x + (size_t)tok * kC);
    uint32_t* dh = g_xg + (size_t)pos * (kC / 2);
    uint32_t* dl = dh + kXPlane;
#pragma unroll
    for (int g = 0; g < 16; g++) {
        float2 v = src[g * 32 + lane];
        uint32_t hp, lp;
        split_pack(v.x, v.y, hp, lp);
        dh[g * 32 + lane] = hp;
        dl[g * 32 + lane] = lp;
    }
}

// ---------------- grouped GEMM: pre-split A (LDG/STS), B fp32 + in-kernel split
// SECOND=false: g_h(planes) = gelu(xg @ W1[e] + b1)
// SECOND=true : out[perm[r]] = prob * (h @ W2[e] + b2)
template <bool SECOND>
__global__ __launch_bounds__(256)
void moe_mma(const float* __restrict__ Wsrc, const float* __restrict__ bias,
             float* __restrict__ OutP) {
    constexpr int KDIM = SECOND ? kH : kC;
    constexpr int ND   = SECOND ? kC : kH;
    constexpr int KB   = KDIM / 16;
    constexpr int KW   = KDIM / 2;                 // u32 per row in a plane

    extern __shared__ char smc[];
    const uint32_t sb = smem_u32(smc);

    const int rt = blockIdx.y, bx = blockIdx.x;
    const int row0 = rt * kBM;
    if (row0 >= g_poff[kE]) return;
    int e = 0;
    while (e < kE - 1 && row0 >= g_poff[e + 1]) e++;

    const uint32_t* Ahi = (SECOND ? g_h : g_xg) + (size_t)row0 * KW;
    const uint32_t* Alo = Ahi + (SECOND ? kHPlane : kXPlane);
    const float*    B   = Wsrc + (size_t)e * KDIM * ND + (size_t)bx * kBN;

    const int tid  = threadIdx.x;
    const int warp = tid >> 5;
    const int lane = tid & 31;
    const int wm   = warp & 3;
    const int wn   = warp >> 2;

    // A fill: thread -> (row, 16B half)
    const int arow = tid >> 1, ah = tid & 1;
    const uint32_t* AhiP = Ahi + (size_t)arow * KW + ah * 4;
    const uint32_t* AloP = Alo + (size_t)arow * KW + ah * 4;
    char* const adst = smc + (size_t)arow * 48 + (size_t)ah * 16;

    // B fill: thread -> (n col, k octet)
    const int bn = tid & 127, bkp = tid >> 7;
    const float* Bload = B + (size_t)bkp * 8 * ND + bn;
    char* const bdst = smc + 2 * kRegB + (size_t)bn * 48 + (size_t)bkp * 16;

    uint4 ah4, al4, ah42, al42;
    float rb[8], rb2[8];
    auto loadA = [&](int kb, uint4& h4, uint4& l4) {
        h4 = *(const uint4*)(AhiP + kb * 8);
        l4 = *(const uint4*)(AloP + kb * 8);
    };
    auto storeA = [&](int s, const uint4& h4, const uint4& l4) {
        *(uint4*)(adst + (size_t)s * kStageB)         = h4;
        *(uint4*)(adst + (size_t)s * kStageB + kRegB) = l4;
    };
    auto loadB = [&](int kb, float* b) {
#pragma unroll
        for (int i = 0; i < 8; i++)
            b[i] = Bload[(size_t)(kb * 16 + i) * ND];
    };
    auto storeB = [&](int s, const float* b) {
        char* base = bdst + (size_t)s * kStageB;
#pragma unroll
        for (int i = 0; i < 4; i++) {
            uint32_t hp, lp;
            split_pack(b[2 * i], b[2 * i + 1], hp, lp);
            *(uint32_t*)(base + i * 4)         = hp;
            *(uint32_t*)(base + kRegB + i * 4) = lp;
        }
    };

    // ldmatrix byte offsets within one region (row stride 48B)
    uint32_t offA[2], offB[4];
#pragma unroll
    for (int i = 0; i < 2; i++) {
        uint32_t row = wm * 32 + i * 16 + ((lane >> 3) & 1) * 8 + (lane & 7);
        offA[i] = row * 48 + (lane >> 4) * 16;
    }
#pragma unroll
    for (int jp = 0; jp < 4; jp++) {
        uint32_t row = wn * 64 + jp * 16 + (lane >> 4) * 8 + (lane & 7);
        offB[jp] = row * 48 + ((lane >> 3) & 1) * 16;
    }

    float acc[2][8][4];
#pragma unroll
    for (int i = 0; i < 2; i++)
#pragma unroll
        for (int j = 0; j < 8; j++)
#pragma unroll
            for (int q = 0; q < 4; q++) acc[i][j][q] = 0.f;

    loadA(0, ah4, al4);
    loadB(0, rb);
    storeA(0, ah4, al4);
    storeB(0, rb);
    __syncthreads();
    loadA(1, ah4, al4);
    loadB(1, rb);

    for (int kb = 0; kb < KB; kb++) {
        const int s = kb & 1;
        if (kb + 1 < KB) {
            storeA(s ^ 1, ah4, al4);
            storeB(s ^ 1, rb);
        }
        if (kb + 2 < KB) {
            loadA(kb + 2, ah42, al42);
            loadB(kb + 2, rb2);
        }

        const uint32_t st = sb + (uint32_t)s * kStageB;
        uint32_t ahi[2][4], alo[2][4], bhi[4][4], blo[4][4];
#pragma unroll
        for (int i = 0; i < 2; i++) {
            LDSM4(ahi[i], st + offA[i]);
            LDSM4(alo[i], st + (uint32_t)kRegB + offA[i]);
        }
#pragma unroll
        for (int jp = 0; jp < 4; jp++) {
            LDSM4(bhi[jp], st + 2u * kRegB + offB[jp]);
            LDSM4(blo[jp], st + 3u * kRegB + offB[jp]);
        }
#pragma unroll
        for (int i = 0; i < 2; i++)
#pragma unroll
            for (int j = 0; j < 8; j++) {
                int jp = j >> 1, s2 = (j & 1) * 2;
                mma16816(acc[i][j], ahi[i], &bhi[jp][s2]);
                mma16816(acc[i][j], ahi[i], &blo[jp][s2]);
                mma16816(acc[i][j], alo[i], &bhi[jp][s2]);
            }
        ah4 = ah42; al4 = al42;
#pragma unroll
        for (int q = 0; q < 8; q++) rb[q] = rb2[q];
        __syncthreads();
    }

    // ---------------- epilogue ----------------
    const int realEnd = g_poff[e] + g_cnt[e];
    const float* biasE = bias + (size_t)e * ND + (size_t)bx * kBN;
    const int r0 = wm * 32 + (lane >> 2);
    const int c0 = (lane & 3) * 2;

#pragma unroll
    for (int i = 0; i < 2; i++)
#pragma unroll
        for (int hh = 0; hh < 2; hh++) {
            int r = row0 + r0 + i * 16 + hh * 8;
            if (r >= realEnd) continue;
            if (!SECOND) {
                uint32_t* hrh = g_h + (size_t)r * (kH / 2) + (size_t)bx * (kBN / 2);
                uint32_t* hrl = hrh + kHPlane;
#pragma unroll
                for (int j = 0; j < 8; j++) {
                    int col = wn * 64 + j * 8 + c0;
                    float v0 = geluf(acc[i][j][hh * 2 + 0] + biasE[col]);
                    float v1 = geluf(acc[i][j][hh * 2 + 1] + biasE[col + 1]);
                    uint32_t hp, lp;
                    split_pack(v0, v1, hp, lp);
                    hrh[col >> 1] = hp;
                    hrl[col >> 1] = lp;
                }
            } else {
                int n = g_perm[r];
                float sc = g_prob[n];
                float* orow = OutP + (size_t)n * kC + (size_t)bx * kBN;
#pragma unroll
                for (int j = 0; j < 8; j++) {
                    int col = wn * 64 + j * 8 + c0;
                    float2 v;
                    v.x = (acc[i][j][hh * 2 + 0] + biasE[col]) * sc;
                    v.y = (acc[i][j][hh * 2 + 1] + biasE[col + 1]) * sc;
                    *(float2*)(orow + col) = v;
                }
            }
        }
}

// ---------------- launch ----------------
extern "C" void kernel_launch(void* const* d_in, const int* in_sizes, int n_in,
                              void* d_out, int out_size) {
    const float* x  = (const float*)d_in[0];
    const float* Wr = (const float*)d_in[1];
    const float* br = (const float*)d_in[2];
    const float* W1 = (const float*)d_in[3];
    const float* b1 = (const float*)d_in[4];
    const float* W2 = (const float*)d_in[5];
    const float* b2 = (const float*)d_in[6];
    float* out = (float*)d_out;
    (void)n_in;

    reset_kernel<<<1, 32>>>();
    router_kernel<<<kN / 8, 256>>>(x, Wr, br);
    float* auxp = (out_size > kN * kC) ? out + (size_t)kN * kC : nullptr;
    offsets_kernel<<<1, 1>>>(auxp);
    gather_kernel<<<kN / 8, 256>>>(x);

    moe_mma<false><<<dim3(kH / kBN, kNRT), 256, kDynSmem>>>(W1, b1, nullptr);
    moe_mma<true ><<<dim3(kC / kBN, kNRT), 256, kDynSmem>>>(W2, b2, out);
}